// round 16
// baseline (speedup 1.0000x reference)
#include <cuda_runtime.h>
#include <cuda_bf16.h>
#include <math.h>
#include <stdint.h>

#define Bsz 2
#define S 2048
#define H 1024
#define NH 16
#define HD 64

// Scratch (allocation-free rule: __device__ globals)
__device__ float g_cos[S * 32];
__device__ float g_sin[S * 32];
__device__ float g_pm[Bsz * NH * 16 * S];   // partial row-max per key-tile
__device__ float g_pl[Bsz * NH * 16 * S];   // partial row-sum per key-tile
__device__ float g_M[Bsz * NH * S];
__device__ float g_iL[Bsz * NH * S];
// split-bf16 buffers
__device__ __nv_bfloat16 g_xh[Bsz * S * H];
__device__ __nv_bfloat16 g_xl[Bsz * S * H];
__device__ __nv_bfloat16 g_ch[Bsz * S * H];
__device__ __nv_bfloat16 g_cl[Bsz * S * H];
__device__ __nv_bfloat16 g_wh[4 * H * H];   // Wq,Wk,Wv rows 0..3H; Wo at 3*HH
__device__ __nv_bfloat16 g_wl[4 * H * H];
__device__ __nv_bfloat16 g_qh[Bsz * S * H];
__device__ __nv_bfloat16 g_ql[Bsz * S * H];
__device__ __nv_bfloat16 g_kh[Bsz * S * H];
__device__ __nv_bfloat16 g_kl[Bsz * S * H];
__device__ __nv_bfloat16 g_vh[Bsz * S * H];
__device__ __nv_bfloat16 g_vl[Bsz * S * H];

// ---------------------------------------------------------------------------
__global__ __launch_bounds__(256) void splitx_table(const float* __restrict__ src,
                                                    __nv_bfloat16* __restrict__ hi,
                                                    __nv_bfloat16* __restrict__ lo) {
    int idx = blockIdx.x * 256 + threadIdx.x;
    if (idx < S * 32) {
        int d = idx & 31;
        int s = idx >> 5;
        double inv = pow(10000.0, -(double)(2 * d) / 64.0);
        double ang = (double)s * inv;
        double sd, cd;
        sincos(ang, &sd, &cd);
        g_cos[idx] = (float)cd;
        g_sin[idx] = (float)sd;
    }
    int i = idx * 4;
    if (i >= Bsz * S * H) return;
    float4 v = *(const float4*)(src + i);
    __nv_bfloat16 h0 = __float2bfloat16(v.x);
    __nv_bfloat16 h1 = __float2bfloat16(v.y);
    __nv_bfloat16 h2 = __float2bfloat16(v.z);
    __nv_bfloat16 h3 = __float2bfloat16(v.w);
    *(__nv_bfloat162*)(hi + i)     = __halves2bfloat162(h0, h1);
    *(__nv_bfloat162*)(hi + i + 2) = __halves2bfloat162(h2, h3);
    *(__nv_bfloat162*)(lo + i)     = __halves2bfloat162(__float2bfloat16(v.x - __bfloat162float(h0)),
                                                        __float2bfloat16(v.y - __bfloat162float(h1)));
    *(__nv_bfloat162*)(lo + i + 2) = __halves2bfloat162(__float2bfloat16(v.z - __bfloat162float(h2)),
                                                        __float2bfloat16(v.w - __bfloat162float(h3)));
}

// ---------------------------------------------------------------------------
__global__ __launch_bounds__(256) void split_w4(const float* __restrict__ w0,
                                                const float* __restrict__ w1,
                                                const float* __restrict__ w2,
                                                const float* __restrict__ w3,
                                                __nv_bfloat16* __restrict__ hi,
                                                __nv_bfloat16* __restrict__ lo) {
    const int HH = H * H;
    int y = blockIdx.y;
    const float* src = (y == 0) ? w0 : (y == 1) ? w1 : (y == 2) ? w2 : w3;
    int i = (blockIdx.x * 256 + threadIdx.x) * 4;
    if (i >= HH) return;
    float4 v = *(const float4*)(src + i);
    __nv_bfloat16* hp = hi + (size_t)y * HH;
    __nv_bfloat16* lp = lo + (size_t)y * HH;
    __nv_bfloat16 h0 = __float2bfloat16(v.x);
    __nv_bfloat16 h1 = __float2bfloat16(v.y);
    __nv_bfloat16 h2 = __float2bfloat16(v.z);
    __nv_bfloat16 h3 = __float2bfloat16(v.w);
    *(__nv_bfloat162*)(hp + i)     = __halves2bfloat162(h0, h1);
    *(__nv_bfloat162*)(hp + i + 2) = __halves2bfloat162(h2, h3);
    *(__nv_bfloat162*)(lp + i)     = __halves2bfloat162(__float2bfloat16(v.x - __bfloat162float(h0)),
                                                        __float2bfloat16(v.y - __bfloat162float(h1)));
    *(__nv_bfloat162*)(lp + i + 2) = __halves2bfloat162(__float2bfloat16(v.z - __bfloat162float(h2)),
                                                        __float2bfloat16(v.w - __bfloat162float(h3)));
}

// ---------------------------------------------------------------------------
// MMA / async-copy helpers (portable ISA only; tcgen05 unavailable at
// compute_103 non-'a' — ptxas rejects it).
// ---------------------------------------------------------------------------
__device__ __forceinline__ void ldsm_x4(uint32_t (&r)[4], uint32_t addr) {
    asm volatile("ldmatrix.sync.aligned.m8n8.x4.shared.b16 {%0,%1,%2,%3}, [%4];"
                 : "=r"(r[0]), "=r"(r[1]), "=r"(r[2]), "=r"(r[3]) : "r"(addr));
}
__device__ __forceinline__ void ldsm_x4_t(uint32_t (&r)[4], uint32_t addr) {
    asm volatile("ldmatrix.sync.aligned.m8n8.x4.trans.shared.b16 {%0,%1,%2,%3}, [%4];"
                 : "=r"(r[0]), "=r"(r[1]), "=r"(r[2]), "=r"(r[3]) : "r"(addr));
}
__device__ __forceinline__ void mma16816(float (&c)[4], const uint32_t (&a)[4],
                                         uint32_t b0, uint32_t b1) {
    asm volatile(
        "mma.sync.aligned.m16n8k16.row.col.f32.bf16.bf16.f32 "
        "{%0,%1,%2,%3}, {%4,%5,%6,%7}, {%8,%9}, {%0,%1,%2,%3};"
        : "+f"(c[0]), "+f"(c[1]), "+f"(c[2]), "+f"(c[3])
        : "r"(a[0]), "r"(a[1]), "r"(a[2]), "r"(a[3]), "r"(b0), "r"(b1));
}
__device__ __forceinline__ void cp16(uint32_t smem, const void* g) {
    asm volatile("cp.async.ca.shared.global [%0], [%1], 16;" :: "r"(smem), "l"(g));
}
__device__ __forceinline__ uint32_t packbf2(__nv_bfloat16 a, __nv_bfloat16 b) {
    __nv_bfloat162 t = __halves2bfloat162(a, b);
    return *(uint32_t*)&t;
}
__device__ __forceinline__ void split_store2(__nv_bfloat16* dh, __nv_bfloat16* dl,
                                             size_t o, float v0, float v1) {
    __nv_bfloat16 h0 = __float2bfloat16(v0);
    __nv_bfloat16 h1 = __float2bfloat16(v1);
    *(uint32_t*)(dh + o) = packbf2(h0, h1);
    *(uint32_t*)(dl + o) = packbf2(__float2bfloat16(v0 - __bfloat162float(h0)),
                                   __float2bfloat16(v1 - __bfloat162float(h1)));
}

// ---------------------------------------------------------------------------
// Split-bf16 GEMM (unchanged from R12).
// ---------------------------------------------------------------------------
template <bool QKV>
__global__ __launch_bounds__(256, 1) void gemm_nt_split(
    const __nv_bfloat16* __restrict__ Ah, const __nv_bfloat16* __restrict__ Al,
    const __nv_bfloat16* __restrict__ Bh, const __nv_bfloat16* __restrict__ Bl,
    float* __restrict__ C,
    __nv_bfloat16* __restrict__ qh, __nv_bfloat16* __restrict__ ql,
    __nv_bfloat16* __restrict__ kh, __nv_bfloat16* __restrict__ kl,
    __nv_bfloat16* __restrict__ vh, __nv_bfloat16* __restrict__ vl,
    int M, int N, int K) {
    __shared__ __align__(16) __nv_bfloat16 sA[2][2][128][72];
    __shared__ __align__(16) __nv_bfloat16 sB[2][2][128][72];

    const int tid = threadIdx.x;
    const int wid = tid >> 5, lane = tid & 31;
    const int wm = (wid & 3) * 32;
    const int wn = (wid >> 2) * 64;
    const int m0 = blockIdx.y * 128, n0 = blockIdx.x * 128;
    const int KSTEPS = K >> 6;

    float acc[2][8][4] = {};
    const uint32_t aBase = (uint32_t)__cvta_generic_to_shared(&sA[0][0][0][0]);
    const uint32_t bBase = (uint32_t)__cvta_generic_to_shared(&sB[0][0][0][0]);
    const uint32_t HL  = 128u * 72u * 2u;
    const uint32_t STG = 2u * HL;

    auto load_stage = [&](int st, int kg) {
#pragma unroll
        for (int i = 0; i < 4; i++) {
            int c = tid + i * 256;
            int row = c >> 3, kc = (c & 7) * 8;
            uint32_t off = (uint32_t)(row * 72 + kc) * 2;
            cp16(aBase + st * STG + off,      Ah + (size_t)(m0 + row) * K + kg + kc);
            cp16(aBase + st * STG + HL + off, Al + (size_t)(m0 + row) * K + kg + kc);
            cp16(bBase + st * STG + off,      Bh + (size_t)(n0 + row) * K + kg + kc);
            cp16(bBase + st * STG + HL + off, Bl + (size_t)(n0 + row) * K + kg + kc);
        }
        asm volatile("cp.async.commit_group;");
    };

    load_stage(0, 0);

    int st = 0;
    for (int kidx = 0; kidx < KSTEPS; kidx++) {
        if (kidx + 1 < KSTEPS) {
            load_stage(st ^ 1, (kidx + 1) * 64);
            asm volatile("cp.async.wait_group 1;");
        } else {
            asm volatile("cp.async.wait_group 0;");
        }
        __syncthreads();

        uint32_t aST = aBase + st * STG;
        uint32_t bST = bBase + st * STG;

#pragma unroll
        for (int s = 0; s < 4; s++) {
            uint32_t aH[2][4], aL[2][4], bF[4][4];
#pragma unroll
            for (int mt = 0; mt < 2; mt++) {
                int row = wm + mt * 16 + (lane & 15);
                int koff = s * 16 + (lane >> 4) * 8;
                uint32_t ad = aST + (uint32_t)(row * 72 + koff) * 2;
                ldsm_x4(aH[mt], ad);
                ldsm_x4(aL[mt], ad + HL);
            }
            {
                int rowp = wn + ((lane >> 4) & 1) * 8 + (lane & 7);
                int koff = s * 16 + ((lane >> 3) & 1) * 8;
#pragma unroll
                for (int p = 0; p < 4; p++)
                    ldsm_x4(bF[p], bST + (uint32_t)((rowp + p * 16) * 72 + koff) * 2);
            }
#pragma unroll
            for (int mt = 0; mt < 2; mt++)
#pragma unroll
                for (int nt = 0; nt < 8; nt++) {
                    uint32_t b0 = bF[nt >> 1][(nt & 1) * 2];
                    uint32_t b1 = bF[nt >> 1][(nt & 1) * 2 + 1];
                    mma16816(acc[mt][nt], aH[mt], b0, b1);
                    mma16816(acc[mt][nt], aL[mt], b0, b1);
                }
            {
                int rowp = wn + ((lane >> 4) & 1) * 8 + (lane & 7);
                int koff = s * 16 + ((lane >> 3) & 1) * 8;
#pragma unroll
                for (int p = 0; p < 4; p++)
                    ldsm_x4(bF[p], bST + (uint32_t)((rowp + p * 16) * 72 + koff) * 2 + HL);
            }
#pragma unroll
            for (int mt = 0; mt < 2; mt++)
#pragma unroll
                for (int nt = 0; nt < 8; nt++) {
                    uint32_t b0 = bF[nt >> 1][(nt & 1) * 2];
                    uint32_t b1 = bF[nt >> 1][(nt & 1) * 2 + 1];
                    mma16816(acc[mt][nt], aH[mt], b0, b1);
                }
        }
        __syncthreads();
        st ^= 1;
    }

    if constexpr (!QKV) {
#pragma unroll
        for (int mt = 0; mt < 2; mt++)
#pragma unroll
            for (int nt = 0; nt < 8; nt++) {
                int r = m0 + wm + mt * 16 + (lane >> 2);
                int cc = n0 + wn + nt * 8 + (lane & 3) * 2;
                *(float2*)(C + (size_t)r * N + cc) = make_float2(acc[mt][nt][0], acc[mt][nt][1]);
                *(float2*)(C + (size_t)(r + 8) * N + cc) = make_float2(acc[mt][nt][2], acc[mt][nt][3]);
            }
    } else {
#pragma unroll
        for (int mt = 0; mt < 2; mt++) {
#pragma unroll
            for (int half = 0; half < 2; half++) {
                int gr = m0 + wm + mt * 16 + (lane >> 2) + half * 8;
                int b = gr >> 11;
                int s = gr & (S - 1);
#pragma unroll
                for (int nt = 0; nt < 4; nt++) {
                    int gc = n0 + wn + nt * 8 + (lane & 3) * 2;
                    int sec = gc >> 10;
                    int hcol = gc & (H - 1);
                    int head = hcol >> 6;
                    int d = hcol & 63;
                    float a0 = acc[mt][nt][half * 2 + 0];
                    float a1 = acc[mt][nt][half * 2 + 1];
                    float b0 = acc[mt][nt + 4][half * 2 + 0];
                    float b1 = acc[mt][nt + 4][half * 2 + 1];
                    float o0, o1, o2, o3;
                    if (sec < 2) {
                        float c0 = g_cos[s * 32 + d],     sn0 = g_sin[s * 32 + d];
                        float c1 = g_cos[s * 32 + d + 1], sn1 = g_sin[s * 32 + d + 1];
                        o0 = a0 * c0 - b0 * sn0;  o2 = b0 * c0 + a0 * sn0;
                        o1 = a1 * c1 - b1 * sn1;  o3 = b1 * c1 + a1 * sn1;
                    } else {
                        o0 = a0; o1 = a1; o2 = b0; o3 = b1;
                    }
                    __nv_bfloat16 *dh, *dl;
                    if (sec == 0)      { dh = qh; dl = ql; }
                    else if (sec == 1) { dh = kh; dl = kl; }
                    else               { dh = vh; dl = vl; }
                    size_t o = ((size_t)(b * NH + head) * S + s) * HD + d;
                    split_store2(dh, dl, o, o0, o1);
                    split_store2(dh, dl, o + 32, o2, o3);
                }
            }
        }
    }
}

// ---------------------------------------------------------------------------
// scores_stats: 128x128 causal tile of raw scores (QK^T/8 + bias, masked),
// written to the attn region, plus per-tile partial row stats (m, l).
// Small blocks (4352 of them) hide latency; based on the proven R7 kernel.
// ---------------------------------------------------------------------------
__global__ __launch_bounds__(256) void scores_stats(
    const __nv_bfloat16* __restrict__ Qh, const __nv_bfloat16* __restrict__ Ql,
    const __nv_bfloat16* __restrict__ Kh, const __nv_bfloat16* __restrict__ Kl,
    const float* __restrict__ bias, const int* __restrict__ mask,
    float* __restrict__ attn, float* __restrict__ pm, float* __restrict__ pl) {
    const int bh = blockIdx.z;
    const int b = bh >> 4;
    const int m0 = blockIdx.y * 128;
    const int n0 = blockIdx.x * 128;
    if (n0 > m0) return;

    __shared__ __align__(16) __nv_bfloat16 sQ[2][128][40];
    __shared__ __align__(16) __nv_bfloat16 sK[2][128][40];
    __shared__ float sStat[2][2][128];
    __shared__ int sMask[128];

    const int tid = threadIdx.x;
    const int wid = tid >> 5, lane = tid & 31;
    const int wm = (wid & 3) * 32;
    const int wg = wid >> 2;
    const int wn = wg * 64;
    const __nv_bfloat16* Qhb = Qh + (size_t)bh * S * HD;
    const __nv_bfloat16* Qlb = Ql + (size_t)bh * S * HD;
    const __nv_bfloat16* Khb = Kh + (size_t)bh * S * HD;
    const __nv_bfloat16* Klb = Kl + (size_t)bh * S * HD;

    if (tid < 128) sMask[tid] = mask[b * S + n0 + tid];

    float acc[2][8][4] = {};
    const uint32_t qBase = (uint32_t)__cvta_generic_to_shared(&sQ[0][0][0]);
    const uint32_t kBase = (uint32_t)__cvta_generic_to_shared(&sK[0][0][0]);

    for (int kk = 0; kk < HD; kk += 32) {
#pragma unroll
        for (int i = 0; i < 2; i++) {
            int c = tid + i * 256;
            int row = c >> 2, kc = (c & 3) * 8;
            *(uint4*)&sQ[0][row][kc] = *(const uint4*)(Qhb + (size_t)(m0 + row) * HD + kk + kc);
            *(uint4*)&sQ[1][row][kc] = *(const uint4*)(Qlb + (size_t)(m0 + row) * HD + kk + kc);
            *(uint4*)&sK[0][row][kc] = *(const uint4*)(Khb + (size_t)(n0 + row) * HD + kk + kc);
            *(uint4*)&sK[1][row][kc] = *(const uint4*)(Klb + (size_t)(n0 + row) * HD + kk + kc);
        }
        __syncthreads();

#pragma unroll
        for (int s = 0; s < 2; s++) {
            uint32_t aH[2][4], aL[2][4], bF[4][4];
#pragma unroll
            for (int mt = 0; mt < 2; mt++) {
                int row = wm + mt * 16 + (lane & 15);
                int koff = s * 16 + (lane >> 4) * 8;
                uint32_t ad = qBase + (uint32_t)(row * 40 + koff) * 2;
                ldsm_x4(aH[mt], ad);
                ldsm_x4(aL[mt], ad + 128 * 40 * 2);
            }
            {
                int rowp = wn + ((lane >> 4) & 1) * 8 + (lane & 7);
                int koff = s * 16 + ((lane >> 3) & 1) * 8;
#pragma unroll
                for (int p = 0; p < 4; p++)
                    ldsm_x4(bF[p], kBase + (uint32_t)((rowp + p * 16) * 40 + koff) * 2);
            }
#pragma unroll
            for (int mt = 0; mt < 2; mt++)
#pragma unroll
                for (int nt = 0; nt < 8; nt++) {
                    uint32_t b0 = bF[nt >> 1][(nt & 1) * 2];
                    uint32_t b1 = bF[nt >> 1][(nt & 1) * 2 + 1];
                    mma16816(acc[mt][nt], aH[mt], b0, b1);
                    mma16816(acc[mt][nt], aL[mt], b0, b1);
                }
            {
                int rowp = wn + ((lane >> 4) & 1) * 8 + (lane & 7);
                int koff = s * 16 + ((lane >> 3) & 1) * 8;
#pragma unroll
                for (int p = 0; p < 4; p++)
                    ldsm_x4(bF[p], kBase + (uint32_t)((rowp + p * 16) * 40 + koff) * 2 + 128 * 40 * 2);
            }
#pragma unroll
            for (int mt = 0; mt < 2; mt++)
#pragma unroll
                for (int nt = 0; nt < 8; nt++) {
                    uint32_t b0 = bF[nt >> 1][(nt & 1) * 2];
                    uint32_t b1 = bF[nt >> 1][(nt & 1) * 2 + 1];
                    mma16816(acc[mt][nt], aH[mt], b0, b1);
                }
        }
        __syncthreads();
    }

    // Raw-score write + per-tile partial stats.
    float mt_[4], lt_[4];
#pragma unroll
    for (int mt = 0; mt < 2; mt++) {
#pragma unroll
        for (int half = 0; half < 2; half++) {
            int rs = mt * 2 + half;
            int r = m0 + wm + mt * 16 + (lane >> 2) + half * 8;
            const float* brow = bias + (size_t)r * S;
            float* arow = attn + ((size_t)bh * S + r) * S;
            float tv[16];
#pragma unroll
            for (int nt = 0; nt < 8; nt++) {
                int cl2 = wn + nt * 8 + (lane & 3) * 2;
                int c = n0 + cl2;
                float2 bv = *(const float2*)(brow + c);
                float s0 = fmaf(acc[mt][nt][half * 2 + 0], 0.125f, bv.x);
                float s1 = fmaf(acc[mt][nt][half * 2 + 1], 0.125f, bv.y);
                if (c > r || sMask[cl2] == 0) s0 = -1e30f;
                if (c + 1 > r || sMask[cl2 + 1] == 0) s1 = -1e30f;
                *(float2*)(arow + c) = make_float2(s0, s1);
                tv[nt * 2] = s0; tv[nt * 2 + 1] = s1;
            }
            float tm = tv[0];
#pragma unroll
            for (int j = 1; j < 16; j++) tm = fmaxf(tm, tv[j]);
            float add = 0.f;
#pragma unroll
            for (int j = 0; j < 16; j++) add += __expf(tv[j] - tm);
            mt_[rs] = tm; lt_[rs] = add;
        }
    }
#pragma unroll
    for (int rs = 0; rs < 4; rs++) {
#pragma unroll
        for (int o = 1; o <= 2; o <<= 1) {
            float mo = __shfl_xor_sync(0xffffffffu, mt_[rs], o);
            float lo = __shfl_xor_sync(0xffffffffu, lt_[rs], o);
            float mn = fmaxf(mt_[rs], mo);
            lt_[rs] = lt_[rs] * __expf(mt_[rs] - mn) + lo * __expf(mo - mn);
            mt_[rs] = mn;
        }
    }
    if ((lane & 3) == 0) {
#pragma unroll
        for (int mt = 0; mt < 2; mt++)
#pragma unroll
            for (int half = 0; half < 2; half++) {
                int rs = mt * 2 + half;
                int row = wm + mt * 16 + (lane >> 2) + half * 8;
                sStat[wg][0][row] = mt_[rs];
                sStat[wg][1][row] = lt_[rs];
            }
    }
    __syncthreads();
    if (tid < 128) {
        float mA = sStat[0][0][tid], lA = sStat[0][1][tid];
        float mB = sStat[1][0][tid], lB = sStat[1][1][tid];
        float M = fmaxf(mA, mB);
        float L = lA * __expf(mA - M) + lB * __expf(mB - M);
        size_t pidx = ((size_t)bh * 16 + (n0 >> 7)) * S + m0 + tid;
        pm[pidx] = M;
        pl[pidx] = L;
    }
}

// ---------------------------------------------------------------------------
// Fold partial stats into final (M, 1/L) per row.
// ---------------------------------------------------------------------------
__global__ __launch_bounds__(256) void stats_merge(const float* __restrict__ pm,
                                                   const float* __restrict__ pl,
                                                   float* __restrict__ gM,
                                                   float* __restrict__ giL) {
    int gid = blockIdx.x * 256 + threadIdx.x;
    if (gid >= Bsz * NH * S) return;
    int bh = gid >> 11;
    int r = gid & (S - 1);
    int si = r >> 7;
    const float* pmb = pm + (size_t)bh * 16 * S + r;
    const float* plb = pl + (size_t)bh * 16 * S + r;
    float M = -1e30f;
    for (int t = 0; t <= si; t++) M = fmaxf(M, pmb[(size_t)t * S]);
    float L = 0.f;
    for (int t = 0; t <= si; t++) L += plb[(size_t)t * S] * __expf(pmb[(size_t)t * S] - M);
    gM[gid] = M;
    giL[gid] = 1.f / L;
}

// ---------------------------------------------------------------------------
// av_norm: normalize raw scores (exp(s-M)*invL), write P back, split to bf16
// in registers, AV MMA, write split ch/cl. Based on the proven R5 av kernel.
// ---------------------------------------------------------------------------
__global__ __launch_bounds__(256) void av_norm(
    float* __restrict__ attn,
    const __nv_bfloat16* __restrict__ Vh, const __nv_bfloat16* __restrict__ Vl,
    const float* __restrict__ gM, const float* __restrict__ giL,
    __nv_bfloat16* __restrict__ ch, __nv_bfloat16* __restrict__ cl) {
    const int bh = blockIdx.z;
    const int b = bh >> 4;
    const int h = bh & 15;
    const int m0 = (int)(gridDim.x - 1 - blockIdx.x) * 128;   // big strips first
    const int kmax = m0 + 128;

    __shared__ __align__(16) __nv_bfloat16 sA[2][128][40];
    __shared__ __align__(16) __nv_bfloat16 sV[2][32][72];

    const int tid = threadIdx.x;
    const int wid = tid >> 5, lane = tid & 31;
    const int wm = (wid & 3) * 32;
    const int wn = (wid >> 2) * 32;
    float* Ab = attn + (size_t)bh * S * S;
    const __nv_bfloat16* Vhb = Vh + (size_t)bh * S * HD;
    const __nv_bfloat16* Vlb = Vl + (size_t)bh * S * HD;

    // Zero the upper-triangle tail of this strip (cols kmax..S).
    {
        int r = tid >> 1;
        float4 z = make_float4(0.f, 0.f, 0.f, 0.f);
        for (int c = kmax + (tid & 1) * 4; c < S; c += 8)
            *(float4*)(Ab + (size_t)(m0 + r) * S + c) = z;
    }

    float acc[2][4][4] = {};
    const uint32_t aBase = (uint32_t)__cvta_generic_to_shared(&sA[0][0][0]);
    const uint32_t vBase = (uint32_t)__cvta_generic_to_shared(&sV[0][0][0]);

    const int arow = tid >> 1;
    const int akc = (tid & 1) * 16;
    const float Mr = gM[bh * S + m0 + arow];
    const float iLr = giL[bh * S + m0 + arow];

    for (int k0 = 0; k0 < kmax; k0 += 32) {
        {   // raw scores -> P (normalize, write back) -> split bf16 -> smem
            float* src = Ab + (size_t)(m0 + arow) * S + k0 + akc;
            float4 f0 = *(const float4*)(src + 0);
            float4 f1 = *(const float4*)(src + 4);
            float4 f2 = *(const float4*)(src + 8);
            float4 f3 = *(const float4*)(src + 12);
            float v[16] = {f0.x, f0.y, f0.z, f0.w, f1.x, f1.y, f1.z, f1.w,
                           f2.x, f2.y, f2.z, f2.w, f3.x, f3.y, f3.z, f3.w};
#pragma unroll
            for (int i = 0; i < 16; i++) v[i] = __expf(v[i] - Mr) * iLr;
            *(float4*)(src + 0)  = make_float4(v[0], v[1], v[2], v[3]);
            *(float4*)(src + 4)  = make_float4(v[4], v[5], v[6], v[7]);
            *(float4*)(src + 8)  = make_float4(v[8], v[9], v[10], v[11]);
            *(float4*)(src + 12) = make_float4(v[12], v[13], v[14], v[15]);
            uint32_t hw[8], lw[8];
#pragma unroll
            for (int i = 0; i < 8; i++) {
                float a0 = v[2 * i], a1 = v[2 * i + 1];
                __nv_bfloat16 h0 = __float2bfloat16(a0);
                __nv_bfloat16 h1 = __float2bfloat16(a1);
                hw[i] = packbf2(h0, h1);
                lw[i] = packbf2(__float2bfloat16(a0 - __bfloat162float(h0)),
                                __float2bfloat16(a1 - __bfloat162float(h1)));
            }
            *(uint4*)&sA[0][arow][akc]     = make_uint4(hw[0], hw[1], hw[2], hw[3]);
            *(uint4*)&sA[0][arow][akc + 8] = make_uint4(hw[4], hw[5], hw[6], hw[7]);
            *(uint4*)&sA[1][arow][akc]     = make_uint4(lw[0], lw[1], lw[2], lw[3]);
            *(uint4*)&sA[1][arow][akc + 8] = make_uint4(lw[4], lw[5], lw[6], lw[7]);
        }
        {
            int row = tid >> 3, col = (tid & 7) * 8;
            *(uint4*)&sV[0][row][col] = *(const uint4*)(Vhb + (size_t)(k0 + row) * HD + col);
            *(uint4*)&sV[1][row][col] = *(const uint4*)(Vlb + (size_t)(k0 + row) * HD + col);
        }
        __syncthreads();

#pragma unroll
        for (int s = 0; s < 2; s++) {
            uint32_t aH[2][4], aL[2][4], bF[2][4];
#pragma unroll
            for (int mt = 0; mt < 2; mt++) {
                int row = wm + mt * 16 + (lane & 15);
                int koff = s * 16 + (lane >> 4) * 8;
                uint32_t ad = aBase + (uint32_t)(row * 40 + koff) * 2;
                ldsm_x4(aH[mt], ad);
                ldsm_x4(aL[mt], ad + 128 * 40 * 2);
            }
            {
                int krow = s * 16 + (lane & 7) + ((lane >> 3) & 1) * 8;
                int col = wn + (lane >> 4) * 8;
#pragma unroll
                for (int p = 0; p < 2; p++) {
                    uint32_t bd = vBase + (uint32_t)(krow * 72 + col + p * 16) * 2;
                    ldsm_x4_t(bF[p], bd);
                }
            }
#pragma unroll
            for (int mt = 0; mt < 2; mt++)
#pragma unroll
                for (int nt = 0; nt < 4; nt++) {
                    uint32_t b0 = bF[nt >> 1][(nt & 1) * 2];
                    uint32_t b1 = bF[nt >> 1][(nt & 1) * 2 + 1];
                    mma16816(acc[mt][nt], aH[mt], b0, b1);   // hi*hi
                    mma16816(acc[mt][nt], aL[mt], b0, b1);   // lo*hi
                }
            {
                int krow = s * 16 + (lane & 7) + ((lane >> 3) & 1) * 8;
                int col = wn + (lane >> 4) * 8;
#pragma unroll
                for (int p = 0; p < 2; p++) {
                    uint32_t bd = vBase + (uint32_t)(krow * 72 + col + p * 16) * 2 + 32 * 72 * 2;
                    ldsm_x4_t(bF[p], bd);
                }
            }
#pragma unroll
            for (int mt = 0; mt < 2; mt++)
#pragma unroll
                for (int nt = 0; nt < 4; nt++) {
                    uint32_t b0 = bF[nt >> 1][(nt & 1) * 2];
                    uint32_t b1 = bF[nt >> 1][(nt & 1) * 2 + 1];
                    mma16816(acc[mt][nt], aH[mt], b0, b1);   // hi*lo
                }
        }
        __syncthreads();
    }

#pragma unroll
    for (int mt = 0; mt < 2; mt++)
#pragma unroll
        for (int nt = 0; nt < 4; nt++) {
            int c = wn + nt * 8 + (lane & 3) * 2;
#pragma unroll
            for (int half = 0; half < 2; half++) {
                int r = m0 + wm + mt * 16 + (lane >> 2) + half * 8;
                size_t oidx = ((size_t)(b * S + r) * NH + h) * HD + c;
                split_store2(ch, cl, oidx,
                             acc[mt][nt][half * 2 + 0], acc[mt][nt][half * 2 + 1]);
            }
        }
}

// ---------------------------------------------------------------------------
extern "C" void kernel_launch(void* const* d_in, const int* in_sizes, int n_in,
                              void* d_out, int out_size) {
    const float* x    = (const float*)d_in[0];
    const int*   mask = (const int*)d_in[1];
    const float* Wq   = (const float*)d_in[2];
    const float* Wk   = (const float*)d_in[3];
    const float* Wv   = (const float*)d_in[4];
    const float* Wo   = (const float*)d_in[5];
    const float* bias = (const float*)d_in[6];

    float* out  = (float*)d_out;
    float* attn = out + (size_t)Bsz * S * H;

    __nv_bfloat16 *xh, *xl, *ch, *cl, *wh, *wl;
    __nv_bfloat16 *qh, *ql, *kh, *kl, *vh, *vl;
    float *pm, *pl, *gM, *giL;
    cudaGetSymbolAddress((void**)&xh, g_xh);
    cudaGetSymbolAddress((void**)&xl, g_xl);
    cudaGetSymbolAddress((void**)&ch, g_ch);
    cudaGetSymbolAddress((void**)&cl, g_cl);
    cudaGetSymbolAddress((void**)&wh, g_wh);
    cudaGetSymbolAddress((void**)&wl, g_wl);
    cudaGetSymbolAddress((void**)&qh, g_qh);
    cudaGetSymbolAddress((void**)&ql, g_ql);
    cudaGetSymbolAddress((void**)&kh, g_kh);
    cudaGetSymbolAddress((void**)&kl, g_kl);
    cudaGetSymbolAddress((void**)&vh, g_vh);
    cudaGetSymbolAddress((void**)&vl, g_vl);
    cudaGetSymbolAddress((void**)&pm, g_pm);
    cudaGetSymbolAddress((void**)&pl, g_pl);
    cudaGetSymbolAddress((void**)&gM, g_M);
    cudaGetSymbolAddress((void**)&giL, g_iL);

    const int M = Bsz * S;                        // 4096
    const int MH = M * H;
    const int HH = H * H;

    splitx_table<<<MH / 4 / 256, 256>>>(x, xh, xl);                            // 1
    split_w4<<<dim3(HH / 4 / 256, 4), 256>>>(Wq, Wk, Wv, Wo, wh, wl);          // 2
    gemm_nt_split<true><<<dim3(3 * H / 128, M / 128), 256>>>(
        xh, xl, wh, wl, nullptr, qh, ql, kh, kl, vh, vl, M, 3 * H, H);         // 3
    scores_stats<<<dim3(S / 128, S / 128, Bsz * NH), 256>>>(
        qh, ql, kh, kl, bias, mask, attn, pm, pl);                             // 4
    stats_merge<<<Bsz * NH * S / 256, 256>>>(pm, pl, gM, giL);                 // 5
    av_norm<<<dim3(S / 128, 1, Bsz * NH), 256>>>(attn, vh, vl, gM, giL,
                                                 ch, cl);                      // 6 <- profiled
    gemm_nt_split<false><<<dim3(H / 128, M / 128), 256>>>(
        ch, cl, wh + 3 * HH, wl + 3 * HH, out,
        nullptr, nullptr, nullptr, nullptr, nullptr, nullptr, M, H, H);        // 7
}

// round 17
// speedup vs baseline: 2.6859x; 2.6859x over previous
#include <cuda_runtime.h>
#include <cuda_bf16.h>
#include <math.h>
#include <stdint.h>

#define Bsz 2
#define S 2048
#define H 1024
#define NH 16
#define HD 64

// Scratch (allocation-free rule: __device__ globals)
__device__ float g_cos[S * 32];
__device__ float g_sin[S * 32];
// split-bf16 buffers
__device__ __nv_bfloat16 g_xh[Bsz * S * H];
__device__ __nv_bfloat16 g_xl[Bsz * S * H];
__device__ __nv_bfloat16 g_ch[Bsz * S * H];
__device__ __nv_bfloat16 g_cl[Bsz * S * H];
__device__ __nv_bfloat16 g_wh[4 * H * H];   // Wq,Wk,Wv rows 0..3H; Wo at 3*HH
__device__ __nv_bfloat16 g_wl[4 * H * H];
__device__ __nv_bfloat16 g_qh[Bsz * S * H];
__device__ __nv_bfloat16 g_ql[Bsz * S * H];
__device__ __nv_bfloat16 g_kh[Bsz * S * H];
__device__ __nv_bfloat16 g_kl[Bsz * S * H];
__device__ __nv_bfloat16 g_vh[Bsz * S * H];
__device__ __nv_bfloat16 g_vl[Bsz * S * H];

// ---------------------------------------------------------------------------
// Fused: split x into hi/lo AND build the RoPE cos/sin table (double prec).
// ---------------------------------------------------------------------------
__global__ __launch_bounds__(256) void splitx_table(const float* __restrict__ src,
                                                    __nv_bfloat16* __restrict__ hi,
                                                    __nv_bfloat16* __restrict__ lo) {
    int idx = blockIdx.x * 256 + threadIdx.x;
    if (idx < S * 32) {
        int d = idx & 31;
        int s = idx >> 5;
        double inv = pow(10000.0, -(double)(2 * d) / 64.0);
        double ang = (double)s * inv;
        double sd, cd;
        sincos(ang, &sd, &cd);
        g_cos[idx] = (float)cd;
        g_sin[idx] = (float)sd;
    }
    int i = idx * 4;
    if (i >= Bsz * S * H) return;
    float4 v = *(const float4*)(src + i);
    __nv_bfloat16 h0 = __float2bfloat16(v.x);
    __nv_bfloat16 h1 = __float2bfloat16(v.y);
    __nv_bfloat16 h2 = __float2bfloat16(v.z);
    __nv_bfloat16 h3 = __float2bfloat16(v.w);
    *(__nv_bfloat162*)(hi + i)     = __halves2bfloat162(h0, h1);
    *(__nv_bfloat162*)(hi + i + 2) = __halves2bfloat162(h2, h3);
    *(__nv_bfloat162*)(lo + i)     = __halves2bfloat162(__float2bfloat16(v.x - __bfloat162float(h0)),
                                                        __float2bfloat16(v.y - __bfloat162float(h1)));
    *(__nv_bfloat162*)(lo + i + 2) = __halves2bfloat162(__float2bfloat16(v.z - __bfloat162float(h2)),
                                                        __float2bfloat16(v.w - __bfloat162float(h3)));
}

// ---------------------------------------------------------------------------
__global__ __launch_bounds__(256) void split_w4(const float* __restrict__ w0,
                                                const float* __restrict__ w1,
                                                const float* __restrict__ w2,
                                                const float* __restrict__ w3,
                                                __nv_bfloat16* __restrict__ hi,
                                                __nv_bfloat16* __restrict__ lo) {
    const int HH = H * H;
    int y = blockIdx.y;
    const float* src = (y == 0) ? w0 : (y == 1) ? w1 : (y == 2) ? w2 : w3;
    int i = (blockIdx.x * 256 + threadIdx.x) * 4;
    if (i >= HH) return;
    float4 v = *(const float4*)(src + i);
    __nv_bfloat16* hp = hi + (size_t)y * HH;
    __nv_bfloat16* lp = lo + (size_t)y * HH;
    __nv_bfloat16 h0 = __float2bfloat16(v.x);
    __nv_bfloat16 h1 = __float2bfloat16(v.y);
    __nv_bfloat16 h2 = __float2bfloat16(v.z);
    __nv_bfloat16 h3 = __float2bfloat16(v.w);
    *(__nv_bfloat162*)(hp + i)     = __halves2bfloat162(h0, h1);
    *(__nv_bfloat162*)(hp + i + 2) = __halves2bfloat162(h2, h3);
    *(__nv_bfloat162*)(lp + i)     = __halves2bfloat162(__float2bfloat16(v.x - __bfloat162float(h0)),
                                                        __float2bfloat16(v.y - __bfloat162float(h1)));
    *(__nv_bfloat162*)(lp + i + 2) = __halves2bfloat162(__float2bfloat16(v.z - __bfloat162float(h2)),
                                                        __float2bfloat16(v.w - __bfloat162float(h3)));
}

// ---------------------------------------------------------------------------
// MMA / async-copy helpers (portable ISA only — tcgen05 is NOT available:
// the harness compiles PTX at compute_103 (non-'a'), ptxas rejects tcgen05).
// ---------------------------------------------------------------------------
__device__ __forceinline__ void ldsm_x4(uint32_t (&r)[4], uint32_t addr) {
    asm volatile("ldmatrix.sync.aligned.m8n8.x4.shared.b16 {%0,%1,%2,%3}, [%4];"
                 : "=r"(r[0]), "=r"(r[1]), "=r"(r[2]), "=r"(r[3]) : "r"(addr));
}
__device__ __forceinline__ void ldsm_x4_t(uint32_t (&r)[4], uint32_t addr) {
    asm volatile("ldmatrix.sync.aligned.m8n8.x4.trans.shared.b16 {%0,%1,%2,%3}, [%4];"
                 : "=r"(r[0]), "=r"(r[1]), "=r"(r[2]), "=r"(r[3]) : "r"(addr));
}
__device__ __forceinline__ void mma16816(float (&c)[4], const uint32_t (&a)[4],
                                         uint32_t b0, uint32_t b1) {
    asm volatile(
        "mma.sync.aligned.m16n8k16.row.col.f32.bf16.bf16.f32 "
        "{%0,%1,%2,%3}, {%4,%5,%6,%7}, {%8,%9}, {%0,%1,%2,%3};"
        : "+f"(c[0]), "+f"(c[1]), "+f"(c[2]), "+f"(c[3])
        : "r"(a[0]), "r"(a[1]), "r"(a[2]), "r"(a[3]), "r"(b0), "r"(b1));
}
__device__ __forceinline__ void cp16(uint32_t smem, const void* g) {
    asm volatile("cp.async.ca.shared.global [%0], [%1], 16;" :: "r"(smem), "l"(g));
}
__device__ __forceinline__ void cp4(uint32_t smem, const void* g) {
    asm volatile("cp.async.ca.shared.global [%0], [%1], 4;" :: "r"(smem), "l"(g));
}
__device__ __forceinline__ uint32_t packbf2(__nv_bfloat16 a, __nv_bfloat16 b) {
    __nv_bfloat162 t = __halves2bfloat162(a, b);
    return *(uint32_t*)&t;
}
__device__ __forceinline__ void split_store2(__nv_bfloat16* dh, __nv_bfloat16* dl,
                                             size_t o, float v0, float v1) {
    __nv_bfloat16 h0 = __float2bfloat16(v0);
    __nv_bfloat16 h1 = __float2bfloat16(v1);
    *(uint32_t*)(dh + o) = packbf2(h0, h1);
    *(uint32_t*)(dl + o) = packbf2(__float2bfloat16(v0 - __bfloat162float(h0)),
                                   __float2bfloat16(v1 - __bfloat162float(h1)));
}

// ---------------------------------------------------------------------------
// Split-bf16 GEMM: C[M,N] = A[M,K] @ B[N,K]^T.
// ---------------------------------------------------------------------------
template <bool QKV>
__global__ __launch_bounds__(256, 1) void gemm_nt_split(
    const __nv_bfloat16* __restrict__ Ah, const __nv_bfloat16* __restrict__ Al,
    const __nv_bfloat16* __restrict__ Bh, const __nv_bfloat16* __restrict__ Bl,
    float* __restrict__ C,
    __nv_bfloat16* __restrict__ qh, __nv_bfloat16* __restrict__ ql,
    __nv_bfloat16* __restrict__ kh, __nv_bfloat16* __restrict__ kl,
    __nv_bfloat16* __restrict__ vh, __nv_bfloat16* __restrict__ vl,
    int M, int N, int K) {
    __shared__ __align__(16) __nv_bfloat16 sA[2][2][128][72];
    __shared__ __align__(16) __nv_bfloat16 sB[2][2][128][72];

    const int tid = threadIdx.x;
    const int wid = tid >> 5, lane = tid & 31;
    const int wm = (wid & 3) * 32;
    const int wn = (wid >> 2) * 64;
    const int m0 = blockIdx.y * 128, n0 = blockIdx.x * 128;
    const int KSTEPS = K >> 6;

    float acc[2][8][4] = {};
    const uint32_t aBase = (uint32_t)__cvta_generic_to_shared(&sA[0][0][0][0]);
    const uint32_t bBase = (uint32_t)__cvta_generic_to_shared(&sB[0][0][0][0]);
    const uint32_t HL  = 128u * 72u * 2u;
    const uint32_t STG = 2u * HL;

    auto load_stage = [&](int st, int kg) {
#pragma unroll
        for (int i = 0; i < 4; i++) {
            int c = tid + i * 256;
            int row = c >> 3, kc = (c & 7) * 8;
            uint32_t off = (uint32_t)(row * 72 + kc) * 2;
            cp16(aBase + st * STG + off,      Ah + (size_t)(m0 + row) * K + kg + kc);
            cp16(aBase + st * STG + HL + off, Al + (size_t)(m0 + row) * K + kg + kc);
            cp16(bBase + st * STG + off,      Bh + (size_t)(n0 + row) * K + kg + kc);
            cp16(bBase + st * STG + HL + off, Bl + (size_t)(n0 + row) * K + kg + kc);
        }
        asm volatile("cp.async.commit_group;");
    };

    load_stage(0, 0);

    int st = 0;
    for (int kidx = 0; kidx < KSTEPS; kidx++) {
        if (kidx + 1 < KSTEPS) {
            load_stage(st ^ 1, (kidx + 1) * 64);
            asm volatile("cp.async.wait_group 1;");
        } else {
            asm volatile("cp.async.wait_group 0;");
        }
        __syncthreads();

        uint32_t aST = aBase + st * STG;
        uint32_t bST = bBase + st * STG;

#pragma unroll
        for (int s = 0; s < 4; s++) {
            uint32_t aH[2][4], aL[2][4], bF[4][4];
#pragma unroll
            for (int mt = 0; mt < 2; mt++) {
                int row = wm + mt * 16 + (lane & 15);
                int koff = s * 16 + (lane >> 4) * 8;
                uint32_t ad = aST + (uint32_t)(row * 72 + koff) * 2;
                ldsm_x4(aH[mt], ad);
                ldsm_x4(aL[mt], ad + HL);
            }
            {
                int rowp = wn + ((lane >> 4) & 1) * 8 + (lane & 7);
                int koff = s * 16 + ((lane >> 3) & 1) * 8;
#pragma unroll
                for (int p = 0; p < 4; p++)
                    ldsm_x4(bF[p], bST + (uint32_t)((rowp + p * 16) * 72 + koff) * 2);
            }
#pragma unroll
            for (int mt = 0; mt < 2; mt++)
#pragma unroll
                for (int nt = 0; nt < 8; nt++) {
                    uint32_t b0 = bF[nt >> 1][(nt & 1) * 2];
                    uint32_t b1 = bF[nt >> 1][(nt & 1) * 2 + 1];
                    mma16816(acc[mt][nt], aH[mt], b0, b1);   // hi*hi
                    mma16816(acc[mt][nt], aL[mt], b0, b1);   // lo*hi
                }
            {
                int rowp = wn + ((lane >> 4) & 1) * 8 + (lane & 7);
                int koff = s * 16 + ((lane >> 3) & 1) * 8;
#pragma unroll
                for (int p = 0; p < 4; p++)
                    ldsm_x4(bF[p], bST + (uint32_t)((rowp + p * 16) * 72 + koff) * 2 + HL);
            }
#pragma unroll
            for (int mt = 0; mt < 2; mt++)
#pragma unroll
                for (int nt = 0; nt < 8; nt++) {
                    uint32_t b0 = bF[nt >> 1][(nt & 1) * 2];
                    uint32_t b1 = bF[nt >> 1][(nt & 1) * 2 + 1];
                    mma16816(acc[mt][nt], aH[mt], b0, b1);   // hi*lo
                }
        }
        __syncthreads();
        st ^= 1;
    }

    if constexpr (!QKV) {
#pragma unroll
        for (int mt = 0; mt < 2; mt++)
#pragma unroll
            for (int nt = 0; nt < 8; nt++) {
                int r = m0 + wm + mt * 16 + (lane >> 2);
                int cc = n0 + wn + nt * 8 + (lane & 3) * 2;
                *(float2*)(C + (size_t)r * N + cc) = make_float2(acc[mt][nt][0], acc[mt][nt][1]);
                *(float2*)(C + (size_t)(r + 8) * N + cc) = make_float2(acc[mt][nt][2], acc[mt][nt][3]);
            }
    } else {
        // RoPE + split epilogue. Pair (nt, nt+4) holds dims (d, d+32).
#pragma unroll
        for (int mt = 0; mt < 2; mt++) {
#pragma unroll
            for (int half = 0; half < 2; half++) {
                int gr = m0 + wm + mt * 16 + (lane >> 2) + half * 8;
                int b = gr >> 11;
                int s = gr & (S - 1);
#pragma unroll
                for (int nt = 0; nt < 4; nt++) {
                    int gc = n0 + wn + nt * 8 + (lane & 3) * 2;
                    int sec = gc >> 10;
                    int hcol = gc & (H - 1);
                    int head = hcol >> 6;
                    int d = hcol & 63;
                    float a0 = acc[mt][nt][half * 2 + 0];
                    float a1 = acc[mt][nt][half * 2 + 1];
                    float b0 = acc[mt][nt + 4][half * 2 + 0];
                    float b1 = acc[mt][nt + 4][half * 2 + 1];
                    float o0, o1, o2, o3;
                    if (sec < 2) {
                        float c0 = g_cos[s * 32 + d],     sn0 = g_sin[s * 32 + d];
                        float c1 = g_cos[s * 32 + d + 1], sn1 = g_sin[s * 32 + d + 1];
                        o0 = a0 * c0 - b0 * sn0;  o2 = b0 * c0 + a0 * sn0;
                        o1 = a1 * c1 - b1 * sn1;  o3 = b1 * c1 + a1 * sn1;
                    } else {
                        o0 = a0; o1 = a1; o2 = b0; o3 = b1;
                    }
                    __nv_bfloat16 *dh, *dl;
                    if (sec == 0)      { dh = qh; dl = ql; }
                    else if (sec == 1) { dh = kh; dl = kl; }
                    else               { dh = vh; dl = vl; }
                    size_t o = ((size_t)(b * NH + head) * S + s) * HD + d;
                    split_store2(dh, dl, o, o0, o1);
                    split_store2(dh, dl, o + 32, o2, o3);
                }
            }
        }
    }
}

// ---------------------------------------------------------------------------
// QK^T 128x128 tile via 3-pass split MMA. Layout: [hi/lo][128][72] at base.
// ---------------------------------------------------------------------------
__device__ __forceinline__ void qk_tile_compute(float (&acc)[2][8][4],
                                                uint32_t qBase, uint32_t kBase,
                                                int wm, int wn, int lane) {
#pragma unroll
    for (int mt = 0; mt < 2; mt++)
#pragma unroll
        for (int nt = 0; nt < 8; nt++)
#pragma unroll
            for (int j = 0; j < 4; j++) acc[mt][nt][j] = 0.f;
#pragma unroll
    for (int s = 0; s < 4; s++) {
        uint32_t aH[2][4], aL[2][4], bF[4][4];
#pragma unroll
        for (int mt = 0; mt < 2; mt++) {
            int row = wm + mt * 16 + (lane & 15);
            int koff = s * 16 + (lane >> 4) * 8;
            uint32_t ad = qBase + (uint32_t)(row * 72 + koff) * 2;
            ldsm_x4(aH[mt], ad);
            ldsm_x4(aL[mt], ad + 128 * 72 * 2);
        }
        int rowp = wn + ((lane >> 4) & 1) * 8 + (lane & 7);
        int koff2 = s * 16 + ((lane >> 3) & 1) * 8;
#pragma unroll
        for (int p = 0; p < 4; p++)
            ldsm_x4(bF[p], kBase + (uint32_t)((rowp + p * 16) * 72 + koff2) * 2);
#pragma unroll
        for (int mt = 0; mt < 2; mt++)
#pragma unroll
            for (int nt = 0; nt < 8; nt++) {
                uint32_t b0 = bF[nt >> 1][(nt & 1) * 2];
                uint32_t b1 = bF[nt >> 1][(nt & 1) * 2 + 1];
                mma16816(acc[mt][nt], aH[mt], b0, b1);
                mma16816(acc[mt][nt], aL[mt], b0, b1);
            }
#pragma unroll
        for (int p = 0; p < 4; p++)
            ldsm_x4(bF[p], kBase + (uint32_t)((rowp + p * 16) * 72 + koff2) * 2 + 128 * 72 * 2);
#pragma unroll
        for (int mt = 0; mt < 2; mt++)
#pragma unroll
            for (int nt = 0; nt < 8; nt++) {
                uint32_t b0 = bF[nt >> 1][(nt & 1) * 2];
                uint32_t b1 = bF[nt >> 1][(nt & 1) * 2 + 1];
                mma16816(acc[mt][nt], aH[mt], b0, b1);
            }
    }
}

// ---------------------------------------------------------------------------
// Fused attention. Pass A: QK MMA once, write RAW biased/masked scores into
// the attn output region while accumulating online (m,l) stats. Pass B: each
// thread re-reads its own raw scores from gmem (same addresses it wrote),
// normalizes to P, writes P back, and feeds the AV MMA. No QK recompute.
// ---------------------------------------------------------------------------
struct KBufs { __nv_bfloat16 k[2][2][128][72]; };
struct OBuf  { float o[128][66]; };
union KOUnion { KBufs kb; OBuf ob; };

__global__ __launch_bounds__(256, 1) void fused_attn(
    const __nv_bfloat16* __restrict__ Qh, const __nv_bfloat16* __restrict__ Ql,
    const __nv_bfloat16* __restrict__ Kh, const __nv_bfloat16* __restrict__ Kl,
    const __nv_bfloat16* __restrict__ Vh, const __nv_bfloat16* __restrict__ Vl,
    const float* __restrict__ bias, const int* __restrict__ mask,
    float* __restrict__ attn,
    __nv_bfloat16* __restrict__ ch, __nv_bfloat16* __restrict__ cl) {
    __shared__ __align__(16) __nv_bfloat16 sQ[2][128][72];
    __shared__ __align__(16) KOUnion uKO;
    __shared__ __align__(16) __nv_bfloat16 sV[2][2][128][72];
    __shared__ float sStat[2][2][128];
    __shared__ float sM[128], sInvL[128];
    __shared__ __align__(16) int sMask[2][128];

    const int bh = blockIdx.y;
    const int b = bh >> 4;
    const int h = bh & 15;
    const int m0 = (int)(gridDim.x - 1 - blockIdx.x) * 128;
    const int kmax = m0 + 128;
    const int NT = kmax >> 7;
    const int tid = threadIdx.x;
    const int wid = tid >> 5, lane = tid & 31;
    const int wm = (wid & 3) * 32;
    const int wg = wid >> 2;
    const int wn = wg * 64;

    const __nv_bfloat16* Qhb = Qh + (size_t)bh * S * HD;
    const __nv_bfloat16* Qlb = Ql + (size_t)bh * S * HD;
    const __nv_bfloat16* Khb = Kh + (size_t)bh * S * HD;
    const __nv_bfloat16* Klb = Kl + (size_t)bh * S * HD;
    const __nv_bfloat16* Vhb = Vh + (size_t)bh * S * HD;
    const __nv_bfloat16* Vlb = Vl + (size_t)bh * S * HD;
    float* attnB = attn + (size_t)bh * S * S;

    const uint32_t qBase = (uint32_t)__cvta_generic_to_shared(&sQ[0][0][0]);
    const uint32_t kBase = (uint32_t)__cvta_generic_to_shared(&uKO.kb.k[0][0][0][0]);
    const uint32_t vBase = (uint32_t)__cvta_generic_to_shared(&sV[0][0][0][0]);
    const uint32_t mBase = (uint32_t)__cvta_generic_to_shared(&sMask[0][0]);
    const uint32_t HL   = 128u * 72u * 2u;
    const uint32_t KBUF = 2u * HL;

    auto load_K = [&](int buf, int n0) {
#pragma unroll
        for (int i = 0; i < 4; i++) {
            int c = tid + i * 256;
            int row = c >> 3, col = (c & 7) * 8;
            uint32_t off = (uint32_t)(row * 72 + col) * 2;
            cp16(kBase + buf * KBUF + off,      Khb + (size_t)(n0 + row) * HD + col);
            cp16(kBase + buf * KBUF + HL + off, Klb + (size_t)(n0 + row) * HD + col);
        }
        if (tid < 128) cp4(mBase + (buf * 128 + tid) * 4, mask + b * S + n0 + tid);
    };
    auto load_V = [&](int buf, int n0) {
#pragma unroll
        for (int i = 0; i < 4; i++) {
            int c = tid + i * 256;
            int row = c >> 3, col = (c & 7) * 8;
            uint32_t off = (uint32_t)(row * 72 + col) * 2;
            cp16(vBase + buf * KBUF + off,      Vhb + (size_t)(n0 + row) * HD + col);
            cp16(vBase + buf * KBUF + HL + off, Vlb + (size_t)(n0 + row) * HD + col);
        }
    };

    // Zero upper-triangle tail of this strip (cols kmax..S).
    {
        int r = tid >> 1;
        float4 z = make_float4(0.f, 0.f, 0.f, 0.f);
        for (int c = kmax + (tid & 1) * 4; c < S; c += 8)
            *(float4*)(attnB + (size_t)(m0 + r) * S + c) = z;
    }

    // Load Q strip once.
#pragma unroll
    for (int i = 0; i < 4; i++) {
        int c = tid + i * 256;
        int row = c >> 3, col = (c & 7) * 8;
        *(uint4*)&sQ[0][row][col] = *(const uint4*)(Qhb + (size_t)(m0 + row) * HD + col);
        *(uint4*)&sQ[1][row][col] = *(const uint4*)(Qlb + (size_t)(m0 + row) * HD + col);
    }

    float m_run[4] = {-1e30f, -1e30f, -1e30f, -1e30f};
    float l_run[4] = {};

    // ---------------- PASS A: QK once, write RAW scores, online stats ------
    load_K(0, 0);
    asm volatile("cp.async.commit_group;");
    for (int t = 0; t < NT; t++) {
        int buf = t & 1;
        if (t + 1 < NT) {
            load_K(buf ^ 1, (t + 1) * 128);
            asm volatile("cp.async.commit_group;");
            asm volatile("cp.async.wait_group 1;");
        } else {
            asm volatile("cp.async.wait_group 0;");
        }
        __syncthreads();

        float acc[2][8][4];
        qk_tile_compute(acc, qBase, kBase + buf * KBUF, wm, wn, lane);
        int n0 = t * 128;

#pragma unroll
        for (int mt = 0; mt < 2; mt++) {
#pragma unroll
            for (int half = 0; half < 2; half++) {
                int rs = mt * 2 + half;
                int r = m0 + wm + mt * 16 + (lane >> 2) + half * 8;
                const float* brow = bias + (size_t)r * S;
                float* arow = attnB + (size_t)r * S;
                float tv[16];
#pragma unroll
                for (int nt = 0; nt < 8; nt++) {
                    int cl2 = wn + nt * 8 + (lane & 3) * 2;
                    int c = n0 + cl2;
                    float2 bv = *(const float2*)(brow + c);
                    float s0 = fmaf(acc[mt][nt][half * 2 + 0], 0.125f, bv.x);
                    float s1 = fmaf(acc[mt][nt][half * 2 + 1], 0.125f, bv.y);
                    if (c > r || sMask[buf][cl2] == 0) s0 = -1e30f;
                    if (c + 1 > r || sMask[buf][cl2 + 1] == 0) s1 = -1e30f;
                    *(float2*)(arow + c) = make_float2(s0, s1);   // stash raw scores
                    tv[nt * 2] = s0; tv[nt * 2 + 1] = s1;
                }
                float tm = tv[0];
#pragma unroll
                for (int j = 1; j < 16; j++) tm = fmaxf(tm, tv[j]);
                float mn = fmaxf(m_run[rs], tm);
                float add = 0.f;
#pragma unroll
                for (int j = 0; j < 16; j++) add += __expf(tv[j] - mn);
                l_run[rs] = l_run[rs] * __expf(m_run[rs] - mn) + add;
                m_run[rs] = mn;
            }
        }
        __syncthreads();
    }

    // Merge stats (quad then warp-group).
#pragma unroll
    for (int rs = 0; rs < 4; rs++) {
#pragma unroll
        for (int o = 1; o <= 2; o <<= 1) {
            float mo = __shfl_xor_sync(0xffffffffu, m_run[rs], o);
            float lo = __shfl_xor_sync(0xffffffffu, l_run[rs], o);
            float mn = fmaxf(m_run[rs], mo);
            l_run[rs] = l_run[rs] * __expf(m_run[rs] - mn) + lo * __expf(mo - mn);
            m_run[rs] = mn;
        }
    }
    if ((lane & 3) == 0) {
#pragma unroll
        for (int mt = 0; mt < 2; mt++)
#pragma unroll
            for (int half = 0; half < 2; half++) {
                int rs = mt * 2 + half;
                int row = wm + mt * 16 + (lane >> 2) + half * 8;
                sStat[wg][0][row] = m_run[rs];
                sStat[wg][1][row] = l_run[rs];
            }
    }
    __syncthreads();
    if (tid < 128) {
        float mA = sStat[0][0][tid], lA = sStat[0][1][tid];
        float mB = sStat[1][0][tid], lB = sStat[1][1][tid];
        float M = fmaxf(mA, mB);
        float L = lA * __expf(mA - M) + lB * __expf(mB - M);
        sM[tid] = M;
        sInvL[tid] = 1.f / L;
    }
    __syncthreads();

    float Mr[4], iLr[4];
#pragma unroll
    for (int mt = 0; mt < 2; mt++)
#pragma unroll
        for (int half = 0; half < 2; half++) {
            int rs = mt * 2 + half;
            int row = wm + mt * 16 + (lane >> 2) + half * 8;
            Mr[rs] = sM[row];
            iLr[rs] = sInvL[row];
        }

    // ---------------- PASS B: re-read raw scores, normalize, AV ------------
    float accO[2][8][4] = {};
    load_V(0, 0);
    asm volatile("cp.async.commit_group;");
    for (int t = 0; t < NT; t++) {
        int buf = t & 1;
        if (t + 1 < NT) {
            load_V(buf ^ 1, (t + 1) * 128);
            asm volatile("cp.async.commit_group;");
            asm volatile("cp.async.wait_group 1;");
        } else {
            asm volatile("cp.async.wait_group 0;");
        }
        __syncthreads();

        int n0 = t * 128;
        float acc[2][8][4];
#pragma unroll
        for (int mt = 0; mt < 2; mt++) {
#pragma unroll
            for (int half = 0; half < 2; half++) {
                int rs = mt * 2 + half;
                int r = m0 + wm + mt * 16 + (lane >> 2) + half * 8;
                float* arow = attnB + (size_t)r * S;
#pragma unroll
                for (int nt = 0; nt < 8; nt++) {
                    int c = n0 + wn + nt * 8 + (lane & 3) * 2;
                    float2 raw = *(const float2*)(arow + c);   // own prior write
                    float p0 = __expf(raw.x - Mr[rs]) * iLr[rs];
                    float p1 = __expf(raw.y - Mr[rs]) * iLr[rs];
                    *(float2*)(arow + c) = make_float2(p0, p1);
                    acc[mt][nt][half * 2 + 0] = p0;
                    acc[mt][nt][half * 2 + 1] = p1;
                }
            }
        }

#pragma unroll
        for (int s2 = 0; s2 < 4; s2++) {
            uint32_t bVh[4][4], bVl[4][4];
            int krow = wn + s2 * 16 + (lane & 7) + ((lane >> 3) & 1) * 8;
#pragma unroll
            for (int p = 0; p < 4; p++) {
                int col = (lane >> 4) * 8 + p * 16;
                uint32_t ad = vBase + buf * KBUF + (uint32_t)(krow * 72 + col) * 2;
                ldsm_x4_t(bVh[p], ad);
                ldsm_x4_t(bVl[p], ad + HL);
            }
#pragma unroll
            for (int mt = 0; mt < 2; mt++) {
                uint32_t aP[4], aPl[4];
#pragma unroll
                for (int q2 = 0; q2 < 2; q2++) {
                    int nt = 2 * s2 + q2;
                    float v0 = acc[mt][nt][0], v1 = acc[mt][nt][1];
                    float v2 = acc[mt][nt][2], v3 = acc[mt][nt][3];
                    __nv_bfloat16 h0 = __float2bfloat16(v0), h1 = __float2bfloat16(v1);
                    __nv_bfloat16 h2 = __float2bfloat16(v2), h3 = __float2bfloat16(v3);
                    aP[q2 * 2 + 0] = packbf2(h0, h1);
                    aP[q2 * 2 + 1] = packbf2(h2, h3);
                    aPl[q2 * 2 + 0] = packbf2(__float2bfloat16(v0 - __bfloat162float(h0)),
                                              __float2bfloat16(v1 - __bfloat162float(h1)));
                    aPl[q2 * 2 + 1] = packbf2(__float2bfloat16(v2 - __bfloat162float(h2)),
                                              __float2bfloat16(v3 - __bfloat162float(h3)));
                }
#pragma unroll
                for (int nt = 0; nt < 8; nt++) {
                    uint32_t b0 = bVh[nt >> 1][(nt & 1) * 2];
                    uint32_t b1 = bVh[nt >> 1][(nt & 1) * 2 + 1];
                    mma16816(accO[mt][nt], aP, b0, b1);
                    mma16816(accO[mt][nt], aPl, b0, b1);
                    uint32_t c0 = bVl[nt >> 1][(nt & 1) * 2];
                    uint32_t c1 = bVl[nt >> 1][(nt & 1) * 2 + 1];
                    mma16816(accO[mt][nt], aP, c0, c1);
                }
            }
        }
        __syncthreads();
    }

    // Merge O across warp groups (sO aliases the dead K buffers).
    float (*sO)[66] = uKO.ob.o;
    __syncthreads();
    if (wg == 1) {
#pragma unroll
        for (int mt = 0; mt < 2; mt++)
#pragma unroll
            for (int nt = 0; nt < 8; nt++)
#pragma unroll
                for (int half = 0; half < 2; half++) {
                    int rl = wm + mt * 16 + (lane >> 2) + half * 8;
                    int c = nt * 8 + (lane & 3) * 2;
                    sO[rl][c] = accO[mt][nt][half * 2 + 0];
                    sO[rl][c + 1] = accO[mt][nt][half * 2 + 1];
                }
    }
    __syncthreads();
    if (wg == 0) {
#pragma unroll
        for (int mt = 0; mt < 2; mt++)
#pragma unroll
            for (int nt = 0; nt < 8; nt++)
#pragma unroll
                for (int half = 0; half < 2; half++) {
                    int rl = wm + mt * 16 + (lane >> 2) + half * 8;
                    int c = nt * 8 + (lane & 3) * 2;
                    float o0 = accO[mt][nt][half * 2 + 0] + sO[rl][c];
                    float o1 = accO[mt][nt][half * 2 + 1] + sO[rl][c + 1];
                    size_t oidx = ((size_t)(b * S + m0 + rl) * NH + h) * HD + c;
                    split_store2(ch, cl, oidx, o0, o1);
                }
    }
}

// ---------------------------------------------------------------------------
extern "C" void kernel_launch(void* const* d_in, const int* in_sizes, int n_in,
                              void* d_out, int out_size) {
    const float* x    = (const float*)d_in[0];
    const int*   mask = (const int*)d_in[1];
    const float* Wq   = (const float*)d_in[2];
    const float* Wk   = (const float*)d_in[3];
    const float* Wv   = (const float*)d_in[4];
    const float* Wo   = (const float*)d_in[5];
    const float* bias = (const float*)d_in[6];

    float* out  = (float*)d_out;
    float* attn = out + (size_t)Bsz * S * H;

    __nv_bfloat16 *xh, *xl, *ch, *cl, *wh, *wl;
    __nv_bfloat16 *qh, *ql, *kh, *kl, *vh, *vl;
    cudaGetSymbolAddress((void**)&xh, g_xh);
    cudaGetSymbolAddress((void**)&xl, g_xl);
    cudaGetSymbolAddress((void**)&ch, g_ch);
    cudaGetSymbolAddress((void**)&cl, g_cl);
    cudaGetSymbolAddress((void**)&wh, g_wh);
    cudaGetSymbolAddress((void**)&wl, g_wl);
    cudaGetSymbolAddress((void**)&qh, g_qh);
    cudaGetSymbolAddress((void**)&ql, g_ql);
    cudaGetSymbolAddress((void**)&kh, g_kh);
    cudaGetSymbolAddress((void**)&kl, g_kl);
    cudaGetSymbolAddress((void**)&vh, g_vh);
    cudaGetSymbolAddress((void**)&vl, g_vl);

    const int M = Bsz * S;                        // 4096
    const int MH = M * H;
    const int HH = H * H;

    splitx_table<<<MH / 4 / 256, 256>>>(x, xh, xl);                            // 1
    split_w4<<<dim3(HH / 4 / 256, 4), 256>>>(Wq, Wk, Wv, Wo, wh, wl);          // 2
    gemm_nt_split<true><<<dim3(3 * H / 128, M / 128), 256>>>(
        xh, xl, wh, wl, nullptr, qh, ql, kh, kl, vh, vl, M, 3 * H, H);         // 3
    fused_attn<<<dim3(S / 128, Bsz * NH), 256>>>(qh, ql, kh, kl, vh, vl,
                                                 bias, mask, attn, ch, cl);    // 4
    gemm_nt_split<false><<<dim3(H / 128, M / 128), 256>>>(
        ch, cl, wh + 3 * HH, wl + 3 * HH, out,
        nullptr, nullptr, nullptr, nullptr, nullptr, nullptr, M, H, H);        // 5
}